// round 12
// baseline (speedup 1.0000x reference)
#include <cuda_runtime.h>
#include <cstdint>

typedef unsigned long long ull;
typedef unsigned int u32;

#define L 512
#define H 1024
#define C 2

// Scratch
__device__ float g_ap[L * H];      // a_proj + b1, [l][o]
__device__ float g_bp[L * H];      // b_proj,      [l][o]
__device__ float g_f[L * L * C];   // unsymmetrized logits f[i][j][c]

// ---- packed f32x2 helpers ----
__device__ __forceinline__ ull ffma2(ull a, ull b, ull c) {
    ull d;
    asm("fma.rn.f32x2 %0, %1, %2, %3;" : "=l"(d) : "l"(a), "l"(b), "l"(c));
    return d;
}
__device__ __forceinline__ ull fadd2(ull a, ull b) {
    ull d;
    asm("add.rn.f32x2 %0, %1, %2;" : "=l"(d) : "l"(a), "l"(b));
    return d;
}
__device__ __forceinline__ float2 u2f2(ull u) {
    float2 v;
    asm("mov.b64 {%0, %1}, %2;" : "=f"(v.x), "=f"(v.y) : "l"(u));
    return v;
}
__device__ __forceinline__ ull tanh2(ull x) {
    ull r;
    asm("{\n\t"
        ".reg .f32 lo, hi;\n\t"
        "mov.b64 {lo, hi}, %1;\n\t"
        "tanh.approx.f32 lo, lo;\n\t"
        "tanh.approx.f32 hi, hi;\n\t"
        "mov.b64 %0, {lo, hi};\n\t"
        "}" : "=l"(r) : "l"(x));
    return r;
}
__device__ __forceinline__ u32 smem_u32(const void* p) {
    u32 a;
    asm("{ .reg .u64 tmp; cvta.to.shared.u64 tmp, %1; cvt.u32.u64 %0, tmp; }"
        : "=r"(a) : "l"(p));
    return a;
}
__device__ __forceinline__ void mma_tf32(float c[4], u32 a0, u32 a1, u32 a2, u32 a3,
                                         u32 b0, u32 b1) {
    asm("mma.sync.aligned.m16n8k8.row.col.f32.tf32.tf32.f32 "
        "{%0,%1,%2,%3}, {%4,%5,%6,%7}, {%8,%9}, {%0,%1,%2,%3};"
        : "+f"(c[0]), "+f"(c[1]), "+f"(c[2]), "+f"(c[3])
        : "r"(a0), "r"(a1), "r"(a2), "r"(a3), "r"(b0), "r"(b1));
}
__device__ __forceinline__ void ldsm_x4(u32& r0, u32& r1, u32& r2, u32& r3, u32 addr) {
    asm volatile("ldmatrix.sync.aligned.m8n8.x4.shared.b16 {%0,%1,%2,%3}, [%4];"
                 : "=r"(r0), "=r"(r1), "=r"(r2), "=r"(r3) : "r"(addr));
}
__device__ __forceinline__ void cp16(u32 dst, const void* src) {
    asm volatile("cp.async.ca.shared.global [%0], [%1], 16;"
                 :: "r"(dst), "l"(src) : "memory");
}
#define CP_COMMIT() asm volatile("cp.async.commit_group;" ::: "memory")
#define CP_WAIT1()  asm volatile("cp.async.wait_group 1;" ::: "memory")

// ============================================================
// Kernel 1: tf32 MMA GEMM, cp.async 3-stage pipeline, ldmatrix,
// raw-f32-as-tf32 (truncation). CTA 128 thr, tile 32l x 32o,
// both ap/bp. Grid (32,16)=512 CTAs; 13.8KB/stage -> 5 CTAs/SM.
// Warp grid 2m x 2n; warp tile m16 x n16 x {ap,bp}.
// ============================================================
#define B_PAD 36
#define S_WORDS (96 * B_PAD)         // A(32 rows)+WA(32)+WB(32), padded
#define K1_SMEM (3 * S_WORDS * 4)    // 41472 bytes

__global__ __launch_bounds__(128) void k1_mma(const float* __restrict__ x,
                                              const float* __restrict__ W1,
                                              const float* __restrict__ b1) {
    extern __shared__ float sm[];
    const u32 smb = smem_u32(sm);

    const int t = threadIdx.x;
    const int lane = t & 31;
    const int wid = t >> 5;
    const int gid = lane >> 2;
    const int tig = lane & 3;
    const int wm = wid & 1;           // 2 m-warps (16 rows each)
    const int wn = wid >> 1;          // 2 n-warps (16 cols each)
    const int oblk = blockIdx.x * 32;
    const int lblk = blockIdx.y * 32;

    // loader: base row r (0..15), 16B chunk c4
    const int r = t >> 3;
    const int c4 = (t & 7) * 4;
    const float* xg = x + (lblk + r) * H + c4;
    const float* wg = W1 + (oblk + r) * (2 * H) + c4;

    // ldmatrix per-lane offsets (word units within a stage)
    const int q = lane >> 3, l7 = lane & 7;
    // A: rows wm*16 + (q&1)*8 + l7, col-word (q>>1)*4
    const u32 a_off = (u32)((wm * 16 + ((q & 1) << 3) + l7) * B_PAD + ((q >> 1) << 2));
    // B: wa rows 32+, wb rows 64+ selected by q>>1; col-word (q&1)*4
    const u32 b_off = (u32)((32 + (q >> 1) * 32 + wn * 16 + l7) * B_PAD + ((q & 1) << 2));

    float accA[2][4], accB[2][4];
#pragma unroll
    for (int na = 0; na < 2; na++)
#pragma unroll
        for (int k = 0; k < 4; k++) { accA[na][k] = 0.f; accB[na][k] = 0.f; }

#define PREFETCH(chunk)                                                     \
    do {                                                                    \
        const int kb = (chunk) * 32;                                        \
        const u32 sb = smb + ((chunk) % 3) * S_WORDS * 4;                   \
        _Pragma("unroll")                                                   \
        for (int qq = 0; qq < 2; qq++) {                                    \
            cp16(sb + ((r + 16 * qq) * B_PAD + c4) * 4,                     \
                 xg + 16 * qq * H + kb);                                    \
            cp16(sb + ((32 + r + 16 * qq) * B_PAD + c4) * 4,                \
                 wg + 16 * qq * (2 * H) + kb);                              \
            cp16(sb + ((64 + r + 16 * qq) * B_PAD + c4) * 4,                \
                 wg + 16 * qq * (2 * H) + kb + H);                          \
        }                                                                   \
    } while (0)

#define COMPUTE(stg)                                                        \
    do {                                                                    \
        const u32 abase = smb + (stg) * S_WORDS * 4 + a_off * 4;            \
        const u32 bbase = smb + (stg) * S_WORDS * 4 + b_off * 4;            \
        _Pragma("unroll")                                                   \
        for (int ks = 0; ks < 4; ks++) {                                    \
            u32 A0, A1, A2, A3;                                             \
            ldsm_x4(A0, A1, A2, A3, abase + (ks * 8) * 4);                  \
            _Pragma("unroll")                                               \
            for (int na = 0; na < 2; na++) {                                \
                u32 B0, B1, B2, B3;                                         \
                ldsm_x4(B0, B1, B2, B3,                                     \
                        bbase + (na * 8 * B_PAD + ks * 8) * 4);             \
                mma_tf32(accA[na], A0, A1, A2, A3, B0, B1);                 \
                mma_tf32(accB[na], A0, A1, A2, A3, B2, B3);                 \
            }                                                               \
        }                                                                   \
    } while (0)

    PREFETCH(0); CP_COMMIT();
    PREFETCH(1); CP_COMMIT();

#pragma unroll 1
    for (int it = 0; it < H / 32; it++) {
        CP_WAIT1();
        __syncthreads();
        if (it + 2 < H / 32) PREFETCH(it + 2);
        CP_COMMIT();
        COMPUTE(it % 3);
    }

    // epilogue: c0=(g,2t) c1=(g,2t+1) c2=(g+8,2t) c3=(g+8,2t+1)
    const int row0 = lblk + wm * 16 + gid;
#pragma unroll
    for (int na = 0; na < 2; na++) {
        const int col = oblk + wn * 16 + na * 8 + tig * 2;
        const float2 bv = *(const float2*)&b1[col];
        float2 v;
        v.x = accA[na][0] + bv.x; v.y = accA[na][1] + bv.y;
        *(float2*)&g_ap[row0 * H + col] = v;
        v.x = accA[na][2] + bv.x; v.y = accA[na][3] + bv.y;
        *(float2*)&g_ap[(row0 + 8) * H + col] = v;
        v.x = accB[na][0]; v.y = accB[na][1];
        *(float2*)&g_bp[row0 * H + col] = v;
        v.x = accB[na][2]; v.y = accB[na][3];
        *(float2*)&g_bp[(row0 + 8) * H + col] = v;
    }
#undef PREFETCH
#undef COMPUTE
}

// ============================================================
// Kernel 2: f[i,j,c] = sum_h tanh(ap[j,h] + bp[i,h]) * W2[c,h]
// Tile 16i x 32j, 256 threads (1i x 2j each), HC=64. MUFU-bound
// at its floor (R3 version, best measured).
// ============================================================
#define P_TI 16
#define P_TJ 32
#define P_HC 64
#define P_PAD 66

__global__ __launch_bounds__(256) void k2_pair(const float* __restrict__ W2) {
    __shared__ __align__(16) float as[P_TJ][P_PAD];   // ap rows (j)
    __shared__ __align__(16) float bs[P_TI][P_PAD];   // bp rows (i)
    __shared__ __align__(16) float w2s[2][P_HC];

    const int t = threadIdx.x;
    const int tx = t & 15;   // j
    const int ty = t >> 4;   // i (16 values)
    const int jblk = blockIdx.x * P_TJ;
    const int iblk = blockIdx.y * P_TI;

    ull acc[2][2];
    acc[0][0] = acc[0][1] = acc[1][0] = acc[1][1] = 0ull;

    for (int hb = 0; hb < H; hb += P_HC) {
#pragma unroll
        for (int qq = 0; qq < 4; qq++) {
            int idx = t + qq * 256;
            int rr = idx >> 5, c = (idx & 31) * 2;
            *(float2*)&as[rr][c] = *(const float2*)&g_ap[(jblk + rr) * H + hb + c];
        }
#pragma unroll
        for (int qq = 0; qq < 2; qq++) {
            int idx = t + qq * 256;
            int rr = idx >> 5, c = (idx & 31) * 2;
            *(float2*)&bs[rr][c] = *(const float2*)&g_bp[(iblk + rr) * H + hb + c];
        }
        if (t < 64) {
            int rr = t >> 5, c = (t & 31) * 2;
            *(float2*)&w2s[rr][c] = *(const float2*)&W2[rr * H + hb + c];
        }
        __syncthreads();

#pragma unroll 16
        for (int hp = 0; hp < P_HC / 2; hp++) {
            ull a0 = *(const ull*)&as[tx][hp * 2];
            ull a1 = *(const ull*)&as[tx + 16][hp * 2];
            ull b0 = *(const ull*)&bs[ty][hp * 2];
            ull w0 = *(const ull*)&w2s[0][hp * 2];
            ull w1 = *(const ull*)&w2s[1][hp * 2];

            ull t0 = tanh2(fadd2(a0, b0));
            ull t1 = tanh2(fadd2(a1, b0));

            acc[0][0] = ffma2(t0, w0, acc[0][0]);
            acc[0][1] = ffma2(t0, w1, acc[0][1]);
            acc[1][0] = ffma2(t1, w0, acc[1][0]);
            acc[1][1] = ffma2(t1, w1, acc[1][1]);
        }
        __syncthreads();
    }

    const int i = iblk + ty;
#pragma unroll
    for (int jv = 0; jv < 2; jv++) {
        const int j = jblk + tx + jv * 16;
        float2 s0 = u2f2(acc[jv][0]);
        float2 s1 = u2f2(acc[jv][1]);
        float2 o;
        o.x = s0.x + s0.y;
        o.y = s1.x + s1.y;
        *(float2*)&g_f[(i * L + j) * 2] = o;
    }
}

// ============================================================
// Kernel 3: out[i,j,c] = 0.5*(f[i,j,c] + f[j,i,c]) + b2[c]
// ============================================================
__global__ __launch_bounds__(256) void k3_sym(const float* __restrict__ b2,
                                              float* __restrict__ out) {
    const int idx = blockIdx.x * 256 + threadIdx.x;
    const int i = idx >> 9;
    const int j = idx & (L - 1);
    const float2 fij = *(const float2*)&g_f[idx * 2];
    const float2 fji = *(const float2*)&g_f[((j << 9) | i) * 2];
    float2 r;
    r.x = (fij.x + fji.x) * 0.5f + b2[0];
    r.y = (fij.y + fji.y) * 0.5f + b2[1];
    *(float2*)&out[idx * 2] = r;
}

extern "C" void kernel_launch(void* const* d_in, const int* in_sizes, int n_in,
                              void* d_out, int out_size) {
    const float* x  = (const float*)d_in[0];
    const float* W1 = (const float*)d_in[1];
    const float* b1 = (const float*)d_in[2];
    const float* W2 = (const float*)d_in[3];
    const float* b2 = (const float*)d_in[4];
    float* out = (float*)d_out;

    cudaFuncSetAttribute(k1_mma, cudaFuncAttributeMaxDynamicSharedMemorySize,
                         K1_SMEM);

    k1_mma<<<dim3(H / 32, L / 32), 128, K1_SMEM>>>(x, W1, b1);
    k2_pair<<<dim3(L / P_TJ, L / P_TI), 256>>>(W2);
    k3_sym<<<(L * L) / 256, 256>>>(b2, out);
}